// round 7
// baseline (speedup 1.0000x reference)
#include <cuda_runtime.h>
#include <cuda_bf16.h>
#include <cstdint>

// ---------------------------------------------------------------------------
// Problem constants
// ---------------------------------------------------------------------------
static constexpr int TOK = 2048;
static constexpr int D   = 1024;
static constexpr int H3  = 3072;
static constexpr int NH  = 16;

// ---------------------------------------------------------------------------
// Scratch (allocation-free)
// ---------------------------------------------------------------------------
__device__ float g_qkv [TOK * H3];
__device__ float g_gate[TOK * D];
__device__ __nv_bfloat16 g_xh [TOK * D],      g_xl [TOK * D];
__device__ __nv_bfloat16 g_wfh[(H3 + D) * D], g_wfl[(H3 + D) * D];  // [Wqkv; Wgate]
__device__ __nv_bfloat16 g_woh[D * D],        g_wol[D * D];
__device__ __nv_bfloat16 g_a2h[TOK * D],      g_a2l[TOK * D];

// ---------------------------------------------------------------------------
// PTX helpers (portable sm_80+ PTX only)
// ---------------------------------------------------------------------------
__device__ __forceinline__ uint32_t smem_u32(const void* p) {
    uint32_t a;
    asm("{ .reg .u64 t; cvta.to.shared.u64 t, %1; cvt.u32.u64 %0, t; }"
        : "=r"(a) : "l"(p));
    return a;
}

#define CP_ASYNC16(dst, src) \
    asm volatile("cp.async.cg.shared.global [%0], [%1], 16;" :: "r"(dst), "l"(src))
#define CP_COMMIT() asm volatile("cp.async.commit_group;" ::: "memory")
#define CP_WAIT1()  asm volatile("cp.async.wait_group 1;"  ::: "memory")

#define LDMX4(r, addr) \
    asm volatile("ldmatrix.sync.aligned.m8n8.x4.shared.b16 {%0,%1,%2,%3}, [%4];" \
                 : "=r"((r)[0]), "=r"((r)[1]), "=r"((r)[2]), "=r"((r)[3]) : "r"(addr))

#define MMA16816(d, a, b0, b1) \
    asm volatile("mma.sync.aligned.m16n8k16.row.col.f32.bf16.bf16.f32 " \
                 "{%0,%1,%2,%3}, {%4,%5,%6,%7}, {%8,%9}, {%0,%1,%2,%3};" \
                 : "+f"((d)[0]), "+f"((d)[1]), "+f"((d)[2]), "+f"((d)[3]) \
                 : "r"((a)[0]), "r"((a)[1]), "r"((a)[2]), "r"((a)[3]), \
                   "r"(b0), "r"(b1))

// ---------------------------------------------------------------------------
// Fused fp32 -> bf16 hi/lo split (one launch for x, Wqkv, Wgate, Wout)
// ---------------------------------------------------------------------------
static constexpr int X4  = TOK * D / 4;
static constexpr int WQ4 = H3 * D / 4;
static constexpr int WG4 = D * D / 4;
static constexpr int WO4 = D * D / 4;
static constexpr int TOT4 = X4 + WQ4 + WG4 + WO4;

__global__ __launch_bounds__(256) void split_all_kernel(
    const float4* __restrict__ x, const float4* __restrict__ wq,
    const float4* __restrict__ wg, const float4* __restrict__ wo,
    uint2* __restrict__ xh, uint2* __restrict__ xl,
    uint2* __restrict__ wfh, uint2* __restrict__ wfl,
    uint2* __restrict__ woh, uint2* __restrict__ wol)
{
    int i = blockIdx.x * 256 + threadIdx.x;
    if (i >= TOT4) return;

    const float4* src; uint2 *dh, *dl; int j;
    if (i < X4)                 { src = x;  dh = xh;  dl = xl;  j = i; }
    else if (i < X4 + WQ4)      { src = wq; dh = wfh; dl = wfl; j = i - X4; }
    else if (i < X4 + WQ4 + WG4){ src = wg; dh = wfh + WQ4; dl = wfl + WQ4; j = i - X4 - WQ4; }
    else                        { src = wo; dh = woh; dl = wol; j = i - X4 - WQ4 - WG4; }

    float4 a = src[j];
    float av[4] = {a.x, a.y, a.z, a.w};
    uint32_t hh[4], ll[4];
#pragma unroll
    for (int k = 0; k < 4; k++) {
        __nv_bfloat16 h = __float2bfloat16(av[k]);
        float r = av[k] - __bfloat162float(h);
        __nv_bfloat16 l = __float2bfloat16(r);
        hh[k] = (uint32_t)__bfloat16_as_ushort(h);
        ll[k] = (uint32_t)__bfloat16_as_ushort(l);
    }
    uint2 hv, lv;
    hv.x = hh[0] | (hh[1] << 16); hv.y = hh[2] | (hh[3] << 16);
    lv.x = ll[0] | (ll[1] << 16); lv.y = ll[2] | (ll[3] << 16);
    dh[j] = hv; dl[j] = lv;
}

// ---------------------------------------------------------------------------
// HMMA GEMM, 3-term bf16 split. CTA tile MTILE x 128, 8 warps,
// warp tile (MTILE/2) x 32, 2-stage cp.async. Dual epilogue (CTA-uniform).
// ---------------------------------------------------------------------------
template <int MTILE>
__global__ __launch_bounds__(256, 2) void hmma_gemm(
    const __nv_bfloat16* __restrict__ Ah, const __nv_bfloat16* __restrict__ Al,
    const __nv_bfloat16* __restrict__ Bh, const __nv_bfloat16* __restrict__ Bl,
    const float* __restrict__ bias0, const float* __restrict__ bias1,
    float* __restrict__ C0, float* __restrict__ C1,
    int N, int K, int NSPLIT)
{
    constexpr int MI  = MTILE / 32;
    constexpr uint32_t ASZ = MTILE * 128;
    constexpr uint32_t STG = ASZ + 16384;

    extern __shared__ char smraw[];
    uint32_t sb = (smem_u32(smraw) + 127u) & ~127u;

    const int tid  = threadIdx.x;
    const int lane = tid & 31;
    const int wid  = tid >> 5;
    const int wm   = wid & 1;
    const int wn   = wid >> 1;
    const int m0 = blockIdx.y * MTILE;
    const int n0 = blockIdx.x * 128;

    const __nv_bfloat16* Aseg[3] = {Ah, Al, Ah};
    const __nv_bfloat16* Bseg[3] = {Bh, Bh, Bl};
    const int kc64   = K >> 6;
    const int nchunk = 3 * kc64;

    float acc[MI][4][4];
#pragma unroll
    for (int i = 0; i < MI; i++)
#pragma unroll
        for (int j = 0; j < 4; j++)
#pragma unroll
            for (int q = 0; q < 4; q++) acc[i][j][q] = 0.f;

    const int a_r  = wm * (MTILE / 2) + ((lane >> 3) & 1) * 8 + (lane & 7);
    const int a_kc = (lane >> 4);
    const int b_r  = wn * 32 + ((lane >> 4) & 1) * 8 + (lane & 7);
    const int b_kc = ((lane >> 3) & 1);

    auto load_tile = [&](int i) {
        const int seg = i / kc64;
        const int kb  = (i - seg * kc64) * 64;
        const int st  = i & 1;
        const uint32_t abase = sb + st * STG;
        const uint32_t bbase = abase + ASZ;
        const __nv_bfloat16* Ag = Aseg[seg];
        const __nv_bfloat16* Bg = Bseg[seg];
#pragma unroll
        for (int t = 0; t < MTILE / 32; t++) {
            int u = tid + t * 256;
            int row = u >> 3, c = u & 7;
            uint32_t dst = abase + (uint32_t)row * 128u + (uint32_t)((c ^ (row & 7)) * 16);
            CP_ASYNC16(dst, (const void*)(Ag + (size_t)(m0 + row) * K + kb + c * 8));
        }
#pragma unroll
        for (int t = 0; t < 4; t++) {
            int u = tid + t * 256;
            int row = u >> 3, c = u & 7;
            uint32_t dst = bbase + (uint32_t)row * 128u + (uint32_t)((c ^ (row & 7)) * 16);
            CP_ASYNC16(dst, (const void*)(Bg + (size_t)(n0 + row) * K + kb + c * 8));
        }
    };

    load_tile(0);
    CP_COMMIT();

    for (int i = 0; i < nchunk; i++) {
        if (i + 1 < nchunk) load_tile(i + 1);
        CP_COMMIT();
        CP_WAIT1();
        __syncthreads();

        const int st = i & 1;
        const uint32_t abase = sb + st * STG;
        const uint32_t bbase = abase + ASZ;

#pragma unroll
        for (int ks = 0; ks < 4; ks++) {
            uint32_t afr[MI][4], bfr[2][4];
#pragma unroll
            for (int mi = 0; mi < MI; mi++) {
                int r = a_r + mi * 16;
                uint32_t addr = abase + (uint32_t)r * 128u
                              + (uint32_t)(((ks * 2 + a_kc) ^ (r & 7)) * 16);
                LDMX4(afr[mi], addr);
            }
#pragma unroll
            for (int ng = 0; ng < 2; ng++) {
                int r = b_r + ng * 16;
                uint32_t addr = bbase + (uint32_t)r * 128u
                              + (uint32_t)(((ks * 2 + b_kc) ^ (r & 7)) * 16);
                LDMX4(bfr[ng], addr);
            }
#pragma unroll
            for (int mi = 0; mi < MI; mi++)
#pragma unroll
                for (int ni = 0; ni < 4; ni++)
                    MMA16816(acc[mi][ni], afr[mi],
                             bfr[ni >> 1][(ni & 1) * 2], bfr[ni >> 1][(ni & 1) * 2 + 1]);
        }
        __syncthreads();
    }

    const bool   gate_tile = (n0 >= NSPLIT);
    float*       Cb    = gate_tile ? C1 : C0;
    const float* bb    = gate_tile ? bias1 : bias0;
    const int    ncols = gate_tile ? (N - NSPLIT) : NSPLIT;
    const int    nb0   = n0 - (gate_tile ? NSPLIT : 0);

    const int mrow = lane >> 2;
    const int ncol = (lane & 3) * 2;
#pragma unroll
    for (int mi = 0; mi < MI; mi++) {
#pragma unroll
        for (int half = 0; half < 2; half++) {
            const int m = m0 + wm * (MTILE / 2) + mi * 16 + mrow + half * 8;
            float* crow = Cb + (size_t)m * ncols;
#pragma unroll
            for (int ni = 0; ni < 4; ni++) {
                const int n = nb0 + wn * 32 + ni * 8 + ncol;
                float v0 = acc[mi][ni][half * 2 + 0] + bb[n];
                float v1 = acc[mi][ni][half * 2 + 1] + bb[n + 1];
                if (gate_tile) {
                    v0 = 1.f / (1.f + __expf(-v0));
                    v1 = 1.f / (1.f + __expf(-v1));
                }
                float2 o = {v0, v1};
                *(float2*)(crow + n) = o;
            }
        }
    }
}

// ---------------------------------------------------------------------------
// Attention, smem-staged, high-parallelism version.
// CTA = (64-token block) x (head), 512 threads / 16 warps, warp does 4 tokens.
// smem: K/V rows [t0-32, t0+64) fp32 = 96 x 64 x 2 x 4B = 48KB.
// Dense offsets 0..32 from smem; 11 sparse offsets from L2.
// ---------------------------------------------------------------------------
__global__ __launch_bounds__(512) void attn_kernel(
    const float* __restrict__ qkv, const float* __restrict__ gate,
    const float* __restrict__ pos_bias,
    __nv_bfloat16* __restrict__ a2h, __nv_bfloat16* __restrict__ a2l)
{
    extern __shared__ float sm[];
    float* sK = sm;               // [96][64]
    float* sV = sm + 96 * 64;     // [96][64]

    const int t0   = blockIdx.x * 64;
    const int h    = blockIdx.y;
    const int tid  = threadIdx.x;
    const int lane = tid & 31;
    const int w    = tid >> 5;

    // stage K/V rows t0-32 .. t0+63 (96 rows x 16 float4 = 1536 chunks)
    for (int idx = tid; idx < 96 * 16; idx += 512) {
        const int row = idx >> 4, c4 = idx & 15;
        const int gt = t0 - 32 + row;
        float4 kv = {0.f, 0.f, 0.f, 0.f}, vv = {0.f, 0.f, 0.f, 0.f};
        if (gt >= 0) {
            kv = *(const float4*)(qkv + (size_t)gt * H3 + D     + h * 64 + c4 * 4);
            vv = *(const float4*)(qkv + (size_t)gt * H3 + 2 * D + h * 64 + c4 * 4);
        }
        *(float4*)(sK + row * 64 + c4 * 4) = kv;
        *(float4*)(sV + row * 64 + c4 * 4) = vv;
    }
    __syncthreads();

    const int offs_sp[12] = {32,48,64,96,128,192,256,384,512,768,1024,1536};
    const float NEG = -1e30f;

#pragma unroll
    for (int it = 0; it < 4; it++) {
        const int n    = t0 + w * 4 + it;
        const int base = (n - t0) + 32;          // smem row for offset 0
        const float2 q2 = *(const float2*)(qkv + (size_t)n * H3 + h * 64 + lane * 2);

        // ---- dense offsets 0..31 from smem ----
        float r[32];
#pragma unroll
        for (int o = 0; o < 32; o++) {
            const float2 k2 = *(const float2*)(sK + (base - o) * 64 + lane * 2);
            r[o] = q2.x * k2.x + q2.y * k2.y;
        }
        // butterfly multi-reduce: lane l ends with sum over lanes of r[l]
#pragma unroll
        for (int m = 16, cnt = 32; m >= 1; m >>= 1, cnt >>= 1) {
            const int half = cnt >> 1;
            const bool hi = (lane & m) != 0;
#pragma unroll
            for (int i = 0; i < 16; i++) {
                if (i < half) {
                    float a = r[i], b = r[i + half];
                    float sel = hi ? a : b;
                    float got = __shfl_xor_sync(0xffffffffu, sel, m);
                    r[i] = hi ? (b + got) : (a + got);
                }
            }
        }
        float s0 = (n - lane >= 0) ? (r[0] * 0.125f + pos_bias[lane * NH + h]) : NEG;

        // ---- sparse offsets (indices 32..43); offset 32 still in smem ----
        float s1 = NEG;
#pragma unroll
        for (int j = 0; j < 12; j++) {
            const int off = offs_sp[j];
            const int src = n - off;
            float sc = NEG;
            if (src >= 0) {
                float2 k2;
                if (off <= 32) k2 = *(const float2*)(sK + (base - off) * 64 + lane * 2);
                else           k2 = *(const float2*)(qkv + (size_t)src * H3 + D + h * 64 + lane * 2);
                float p = q2.x * k2.x + q2.y * k2.y;
                p += __shfl_xor_sync(0xffffffffu, p, 16);
                p += __shfl_xor_sync(0xffffffffu, p, 8);
                p += __shfl_xor_sync(0xffffffffu, p, 4);
                p += __shfl_xor_sync(0xffffffffu, p, 2);
                p += __shfl_xor_sync(0xffffffffu, p, 1);
                sc = p * 0.125f + pos_bias[(32 + j) * NH + h];
            }
            if (lane == j) s1 = sc;
        }

        // ---- softmax over 44 distributed scores ----
        float m = fmaxf(s0, s1);
        m = fmaxf(m, __shfl_xor_sync(0xffffffffu, m, 16));
        m = fmaxf(m, __shfl_xor_sync(0xffffffffu, m, 8));
        m = fmaxf(m, __shfl_xor_sync(0xffffffffu, m, 4));
        m = fmaxf(m, __shfl_xor_sync(0xffffffffu, m, 2));
        m = fmaxf(m, __shfl_xor_sync(0xffffffffu, m, 1));

        float e0 = (s0 > NEG) ? __expf(s0 - m) : 0.f;
        float e1 = (s1 > NEG) ? __expf(s1 - m) : 0.f;

        float sum = e0 + e1;
        sum += __shfl_xor_sync(0xffffffffu, sum, 16);
        sum += __shfl_xor_sync(0xffffffffu, sum, 8);
        sum += __shfl_xor_sync(0xffffffffu, sum, 4);
        sum += __shfl_xor_sync(0xffffffffu, sum, 2);
        sum += __shfl_xor_sync(0xffffffffu, sum, 1);
        const float inv = 1.f / sum;

        // ---- weighted V sum: dense from smem, sparse from L2 ----
        float acc0 = 0.f, acc1 = 0.f;
#pragma unroll
        for (int o = 0; o < 32; o++) {
            float al = __shfl_sync(0xffffffffu, e0, o);
            const float2 v2 = *(const float2*)(sV + (base - o) * 64 + lane * 2);
            acc0 = fmaf(al, v2.x, acc0);
            acc1 = fmaf(al, v2.y, acc1);
        }
#pragma unroll
        for (int j = 0; j < 12; j++) {
            const int off = offs_sp[j];
            const int src = n - off;
            if (src >= 0) {
                float al = __shfl_sync(0xffffffffu, e1, j);
                float2 v2;
                if (off <= 32) v2 = *(const float2*)(sV + (base - off) * 64 + lane * 2);
                else           v2 = *(const float2*)(qkv + (size_t)src * H3 + 2 * D + h * 64 + lane * 2);
                acc0 = fmaf(al, v2.x, acc0);
                acc1 = fmaf(al, v2.y, acc1);
            }
        }
        acc0 *= inv;
        acc1 *= inv;

        const int oi = n * D + h * 64 + lane * 2;
        const float2 g2 = *(const float2*)(gate + oi);
        float v0 = acc0 * g2.x;
        float v1 = acc1 * g2.y;

        __nv_bfloat16 h0 = __float2bfloat16(v0);
        __nv_bfloat16 h1 = __float2bfloat16(v1);
        a2h[oi]     = h0;
        a2h[oi + 1] = h1;
        a2l[oi]     = __float2bfloat16(v0 - __bfloat162float(h0));
        a2l[oi + 1] = __float2bfloat16(v1 - __bfloat162float(h1));
    }
}

// ---------------------------------------------------------------------------
// kernel_launch
// ---------------------------------------------------------------------------
extern "C" void kernel_launch(void* const* d_in, const int* in_sizes, int n_in,
                              void* d_out, int out_size)
{
    const float* x        = (const float*)d_in[0];
    const float* Wqkv     = (const float*)d_in[1];
    const float* bqkv     = (const float*)d_in[2];
    const float* Wout     = (const float*)d_in[3];
    const float* bout     = (const float*)d_in[4];
    const float* Wgate    = (const float*)d_in[5];
    const float* bgate    = (const float*)d_in[6];
    const float* pos_bias = (const float*)d_in[7];
    float* out = (float*)d_out;

    float *qkv, *gate;
    __nv_bfloat16 *xh, *xl, *wfh, *wfl, *woh, *wol, *a2h, *a2l;
    cudaGetSymbolAddress((void**)&qkv,  g_qkv);
    cudaGetSymbolAddress((void**)&gate, g_gate);
    cudaGetSymbolAddress((void**)&xh,  g_xh);  cudaGetSymbolAddress((void**)&xl,  g_xl);
    cudaGetSymbolAddress((void**)&wfh, g_wfh); cudaGetSymbolAddress((void**)&wfl, g_wfl);
    cudaGetSymbolAddress((void**)&woh, g_woh); cudaGetSymbolAddress((void**)&wol, g_wol);
    cudaGetSymbolAddress((void**)&a2h, g_a2h); cudaGetSymbolAddress((void**)&a2l, g_a2l);

    const int SMEM_G128 = 128 + 2 * (128 * 128 + 16384);   // 65664
    const int SMEM_G64  = 128 + 2 * (64 * 128 + 16384);    // 49280
    const int SMEM_ATTN = 96 * 64 * 2 * 4;                 // 49152
    cudaFuncSetAttribute(hmma_gemm<128>, cudaFuncAttributeMaxDynamicSharedMemorySize, SMEM_G128);
    cudaFuncSetAttribute(hmma_gemm<64>,  cudaFuncAttributeMaxDynamicSharedMemorySize, SMEM_G64);
    cudaFuncSetAttribute(attn_kernel,    cudaFuncAttributeMaxDynamicSharedMemorySize, SMEM_ATTN);

    // 1) all fp32 -> bf16 hi/lo splits
    split_all_kernel<<<(TOT4 + 255) / 256, 256>>>(
        (const float4*)x, (const float4*)Wqkv, (const float4*)Wgate, (const float4*)Wout,
        (uint2*)xh, (uint2*)xl, (uint2*)wfh, (uint2*)wfl, (uint2*)woh, (uint2*)wol);

    // 2) fused qkv+gate GEMM: [2048, 4096] = x @ [Wqkv; Wgate]^T
    hmma_gemm<128><<<dim3((H3 + D) / 128, TOK / 128), 256, SMEM_G128>>>(
        xh, xl, wfh, wfl, bqkv, bgate, qkv, gate, H3 + D, D, H3);

    // 3) attention + gate -> split a2   (grid: 32 token blocks x 16 heads)
    attn_kernel<<<dim3(TOK / 64, NH), 512, SMEM_ATTN>>>(qkv, gate, pos_bias, a2h, a2l);

    // 4) out = a2 @ Wout^T + bout  (64-row tiles -> 256 CTAs)
    hmma_gemm<64><<<dim3(D / 128, TOK / 64), 256, SMEM_G64>>>(
        a2h, a2l, woh, wol, bout, bout, out, nullptr, D, D, D);
}

// round 8
// speedup vs baseline: 1.2278x; 1.2278x over previous
#include <cuda_runtime.h>
#include <cuda_bf16.h>
#include <cstdint>

// ---------------------------------------------------------------------------
// Problem constants
// ---------------------------------------------------------------------------
static constexpr int TOK = 2048;
static constexpr int D   = 1024;
static constexpr int H3  = 3072;
static constexpr int NH  = 16;
static constexpr int NOFF = 44;

__device__ __constant__ int c_offs[NOFF] = {
    0,1,2,3,4,5,6,7,8,9,10,11,12,13,14,15,16,17,18,19,20,21,22,23,24,
    25,26,27,28,29,30,31,32,48,64,96,128,192,256,384,512,768,1024,1536};

// ---------------------------------------------------------------------------
// Scratch (allocation-free)
// ---------------------------------------------------------------------------
__device__ float g_qkv [TOK * H3];
__device__ float g_gate[TOK * D];
__device__ __nv_bfloat16 g_xh [TOK * D],      g_xl [TOK * D];
__device__ __nv_bfloat16 g_wfh[(H3 + D) * D], g_wfl[(H3 + D) * D];  // [Wqkv; Wgate]
__device__ __nv_bfloat16 g_woh[D * D],        g_wol[D * D];
__device__ __nv_bfloat16 g_a2h[TOK * D],      g_a2l[TOK * D];

// ---------------------------------------------------------------------------
// PTX helpers (portable sm_80+ PTX only)
// ---------------------------------------------------------------------------
__device__ __forceinline__ uint32_t smem_u32(const void* p) {
    uint32_t a;
    asm("{ .reg .u64 t; cvta.to.shared.u64 t, %1; cvt.u32.u64 %0, t; }"
        : "=r"(a) : "l"(p));
    return a;
}

#define CP_ASYNC16(dst, src) \
    asm volatile("cp.async.cg.shared.global [%0], [%1], 16;" :: "r"(dst), "l"(src))
#define CP_COMMIT() asm volatile("cp.async.commit_group;" ::: "memory")
#define CP_WAIT1()  asm volatile("cp.async.wait_group 1;"  ::: "memory")

#define LDMX4(r, addr) \
    asm volatile("ldmatrix.sync.aligned.m8n8.x4.shared.b16 {%0,%1,%2,%3}, [%4];" \
                 : "=r"((r)[0]), "=r"((r)[1]), "=r"((r)[2]), "=r"((r)[3]) : "r"(addr))

#define MMA16816(d, a, b0, b1) \
    asm volatile("mma.sync.aligned.m16n8k16.row.col.f32.bf16.bf16.f32 " \
                 "{%0,%1,%2,%3}, {%4,%5,%6,%7}, {%8,%9}, {%0,%1,%2,%3};" \
                 : "+f"((d)[0]), "+f"((d)[1]), "+f"((d)[2]), "+f"((d)[3]) \
                 : "r"((a)[0]), "r"((a)[1]), "r"((a)[2]), "r"((a)[3]), \
                   "r"(b0), "r"(b1))

// ---------------------------------------------------------------------------
// Fused fp32 -> bf16 hi/lo split (one launch for x, Wqkv, Wgate, Wout)
// ---------------------------------------------------------------------------
static constexpr int X4  = TOK * D / 4;
static constexpr int WQ4 = H3 * D / 4;
static constexpr int WG4 = D * D / 4;
static constexpr int WO4 = D * D / 4;
static constexpr int TOT4 = X4 + WQ4 + WG4 + WO4;

__global__ __launch_bounds__(256) void split_all_kernel(
    const float4* __restrict__ x, const float4* __restrict__ wq,
    const float4* __restrict__ wg, const float4* __restrict__ wo,
    uint2* __restrict__ xh, uint2* __restrict__ xl,
    uint2* __restrict__ wfh, uint2* __restrict__ wfl,
    uint2* __restrict__ woh, uint2* __restrict__ wol)
{
    int i = blockIdx.x * 256 + threadIdx.x;
    if (i >= TOT4) return;

    const float4* src; uint2 *dh, *dl; int j;
    if (i < X4)                 { src = x;  dh = xh;  dl = xl;  j = i; }
    else if (i < X4 + WQ4)      { src = wq; dh = wfh; dl = wfl; j = i - X4; }
    else if (i < X4 + WQ4 + WG4){ src = wg; dh = wfh + WQ4; dl = wfl + WQ4; j = i - X4 - WQ4; }
    else                        { src = wo; dh = woh; dl = wol; j = i - X4 - WQ4 - WG4; }

    float4 a = src[j];
    float av[4] = {a.x, a.y, a.z, a.w};
    uint32_t hh[4], ll[4];
#pragma unroll
    for (int k = 0; k < 4; k++) {
        __nv_bfloat16 h = __float2bfloat16(av[k]);
        float r = av[k] - __bfloat162float(h);
        __nv_bfloat16 l = __float2bfloat16(r);
        hh[k] = (uint32_t)__bfloat16_as_ushort(h);
        ll[k] = (uint32_t)__bfloat16_as_ushort(l);
    }
    uint2 hv, lv;
    hv.x = hh[0] | (hh[1] << 16); hv.y = hh[2] | (hh[3] << 16);
    lv.x = ll[0] | (ll[1] << 16); lv.y = ll[2] | (ll[3] << 16);
    dh[j] = hv; dl[j] = lv;
}

// ---------------------------------------------------------------------------
// HMMA GEMM, all-tiles-staged 3-term split.
// CTA tile 64x128, 8 warps (warp tile 32x32). Per K-chunk (64 wide) stage
// Ah, Al (8KB each) + Bh, Bl (16KB each) = 48KB/stage, 2 stages.
// Per chunk: 3 MMA passes (Ah*Bh, Al*Bh, Ah*Bl) -> one __syncthreads per
// 96 MMAs instead of per 32, and 33% less staging traffic.
// Dual epilogue (CTA-uniform): n<NSPLIT -> C0+bias0 else sigmoid -> C1.
// ---------------------------------------------------------------------------
__global__ __launch_bounds__(256, 2) void hmma_gemm(
    const __nv_bfloat16* __restrict__ Ah, const __nv_bfloat16* __restrict__ Al,
    const __nv_bfloat16* __restrict__ Bh, const __nv_bfloat16* __restrict__ Bl,
    const float* __restrict__ bias0, const float* __restrict__ bias1,
    float* __restrict__ C0, float* __restrict__ C1,
    int N, int K, int NSPLIT)
{
    constexpr uint32_t A_SZ  = 64 * 128;          // 8KB per A tile
    constexpr uint32_t B_SZ  = 128 * 128;         // 16KB per B tile
    constexpr uint32_t OFF_AL = A_SZ;             // 8KB
    constexpr uint32_t OFF_BH = 2 * A_SZ;         // 16KB
    constexpr uint32_t OFF_BL = 2 * A_SZ + B_SZ;  // 32KB
    constexpr uint32_t STG    = 2 * A_SZ + 2 * B_SZ;  // 48KB

    extern __shared__ char smraw[];
    uint32_t sb = (smem_u32(smraw) + 127u) & ~127u;

    const int tid  = threadIdx.x;
    const int lane = tid & 31;
    const int wid  = tid >> 5;
    const int wm   = wid & 1;       // 0..1 -> 32-row slab
    const int wn   = wid >> 1;      // 0..3 -> 32-col slab
    const int m0 = blockIdx.y * 64;
    const int n0 = blockIdx.x * 128;

    const int nchunk = K >> 6;

    float acc[2][4][4];
#pragma unroll
    for (int i = 0; i < 2; i++)
#pragma unroll
        for (int j = 0; j < 4; j++)
#pragma unroll
            for (int q = 0; q < 4; q++) acc[i][j][q] = 0.f;

    const int a_r  = wm * 32 + ((lane >> 3) & 1) * 8 + (lane & 7);
    const int a_kc = (lane >> 4);
    const int b_r  = wn * 32 + ((lane >> 4) & 1) * 8 + (lane & 7);
    const int b_kc = ((lane >> 3) & 1);

    // loader: per stage 512+512+1024+1024 = 3072 chunks of 16B; 12/thread
    auto load_tile = [&](int i) {
        const int kb = i * 64;
        const uint32_t base = sb + (uint32_t)(i & 1) * STG;
        // A hi/lo: 64 rows x 8 chunks
#pragma unroll
        for (int t = 0; t < 2; t++) {
            int u = tid + t * 256;
            int row = u >> 3, c = u & 7;
            uint32_t sw = (uint32_t)row * 128u + (uint32_t)((c ^ (row & 7)) * 16);
            const size_t g = (size_t)(m0 + row) * K + kb + c * 8;
            CP_ASYNC16(base + sw,          (const void*)(Ah + g));
            CP_ASYNC16(base + OFF_AL + sw, (const void*)(Al + g));
        }
        // B hi/lo: 128 rows x 8 chunks
#pragma unroll
        for (int t = 0; t < 4; t++) {
            int u = tid + t * 256;
            int row = u >> 3, c = u & 7;
            uint32_t sw = (uint32_t)row * 128u + (uint32_t)((c ^ (row & 7)) * 16);
            const size_t g = (size_t)(n0 + row) * K + kb + c * 8;
            CP_ASYNC16(base + OFF_BH + sw, (const void*)(Bh + g));
            CP_ASYNC16(base + OFF_BL + sw, (const void*)(Bl + g));
        }
    };

    load_tile(0);
    CP_COMMIT();

    for (int i = 0; i < nchunk; i++) {
        if (i + 1 < nchunk) load_tile(i + 1);
        CP_COMMIT();
        CP_WAIT1();
        __syncthreads();

        const uint32_t base = sb + (uint32_t)(i & 1) * STG;

#pragma unroll
        for (int ks = 0; ks < 4; ks++) {
            const uint32_t a_sw = (uint32_t)(((ks * 2 + a_kc) ^ (a_r & 7)) * 16);
            const uint32_t b_sw = (uint32_t)(((ks * 2 + b_kc) ^ (b_r & 7)) * 16);

            uint32_t afh[2][4], bfh[2][4];
#pragma unroll
            for (int mi = 0; mi < 2; mi++) {
                int r = a_r + mi * 16;
                uint32_t sw = (uint32_t)(((ks * 2 + a_kc) ^ (r & 7)) * 16);
                LDMX4(afh[mi], base + (uint32_t)r * 128u + sw);
            }
#pragma unroll
            for (int ng = 0; ng < 2; ng++) {
                int r = b_r + ng * 16;
                uint32_t sw = (uint32_t)(((ks * 2 + b_kc) ^ (r & 7)) * 16);
                LDMX4(bfh[ng], base + OFF_BH + (uint32_t)r * 128u + sw);
            }
            // pass 1: Ah * Bh
#pragma unroll
            for (int mi = 0; mi < 2; mi++)
#pragma unroll
                for (int ni = 0; ni < 4; ni++)
                    MMA16816(acc[mi][ni], afh[mi],
                             bfh[ni >> 1][(ni & 1) * 2], bfh[ni >> 1][(ni & 1) * 2 + 1]);

            // pass 2: Al * Bh
            {
                uint32_t afl[2][4];
#pragma unroll
                for (int mi = 0; mi < 2; mi++) {
                    int r = a_r + mi * 16;
                    uint32_t sw = (uint32_t)(((ks * 2 + a_kc) ^ (r & 7)) * 16);
                    LDMX4(afl[mi], base + OFF_AL + (uint32_t)r * 128u + sw);
                }
#pragma unroll
                for (int mi = 0; mi < 2; mi++)
#pragma unroll
                    for (int ni = 0; ni < 4; ni++)
                        MMA16816(acc[mi][ni], afl[mi],
                                 bfh[ni >> 1][(ni & 1) * 2], bfh[ni >> 1][(ni & 1) * 2 + 1]);
            }
            // pass 3: Ah * Bl
            {
                uint32_t bfl[2][4];
#pragma unroll
                for (int ng = 0; ng < 2; ng++) {
                    int r = b_r + ng * 16;
                    uint32_t sw = (uint32_t)(((ks * 2 + b_kc) ^ (r & 7)) * 16);
                    LDMX4(bfl[ng], base + OFF_BL + (uint32_t)r * 128u + sw);
                }
#pragma unroll
                for (int mi = 0; mi < 2; mi++)
#pragma unroll
                    for (int ni = 0; ni < 4; ni++)
                        MMA16816(acc[mi][ni], afh[mi],
                                 bfl[ni >> 1][(ni & 1) * 2], bfl[ni >> 1][(ni & 1) * 2 + 1]);
            }
        }
        __syncthreads();
    }

    const bool   gate_tile = (n0 >= NSPLIT);
    float*       Cb    = gate_tile ? C1 : C0;
    const float* bb    = gate_tile ? bias1 : bias0;
    const int    ncols = gate_tile ? (N - NSPLIT) : NSPLIT;
    const int    nb0   = n0 - (gate_tile ? NSPLIT : 0);

    const int mrow = lane >> 2;
    const int ncol = (lane & 3) * 2;
#pragma unroll
    for (int mi = 0; mi < 2; mi++) {
#pragma unroll
        for (int half = 0; half < 2; half++) {
            const int m = m0 + wm * 32 + mi * 16 + mrow + half * 8;
            float* crow = Cb + (size_t)m * ncols;
#pragma unroll
            for (int ni = 0; ni < 4; ni++) {
                const int n = nb0 + wn * 32 + ni * 8 + ncol;
                float v0 = acc[mi][ni][half * 2 + 0] + bb[n];
                float v1 = acc[mi][ni][half * 2 + 1] + bb[n + 1];
                if (gate_tile) {
                    v0 = 1.f / (1.f + __expf(-v0));
                    v1 = 1.f / (1.f + __expf(-v1));
                }
                float2 o = {v0, v1};
                *(float2*)(crow + n) = o;
            }
        }
    }
}

// ---------------------------------------------------------------------------
// Attention (exact R5 winner): one warp per (token, head), lane owns dims
// {2l, 2l+1}; dense offsets via butterfly multi-reduce; global (L2) loads.
// ---------------------------------------------------------------------------
__global__ __launch_bounds__(256) void attn_kernel(
    const float* __restrict__ qkv, const float* __restrict__ gate,
    const float* __restrict__ pos_bias,
    __nv_bfloat16* __restrict__ a2h, __nv_bfloat16* __restrict__ a2l)
{
    const int gwarp = (blockIdx.x * blockDim.x + threadIdx.x) >> 5;
    const int lane  = threadIdx.x & 31;
    const int n = gwarp >> 4;
    const int h = gwarp & 15;
    if (n >= TOK) return;

    const float2 q2 = *(const float2*)(qkv + (size_t)n * H3 + h * 64 + lane * 2);
    const float NEG = -1e30f;

    // ---- dense offsets 0..31 ----
    float r[32];
#pragma unroll
    for (int o = 0; o < 32; o++) {
        const int src = n - o;
        float p = 0.f;
        if (src >= 0) {
            const float2 k2 = *(const float2*)(qkv + (size_t)src * H3 + D + h * 64 + lane * 2);
            p = q2.x * k2.x + q2.y * k2.y;
        }
        r[o] = p;
    }
#pragma unroll
    for (int m = 16, cnt = 32; m >= 1; m >>= 1, cnt >>= 1) {
        const int half = cnt >> 1;
        const bool hi = (lane & m) != 0;
#pragma unroll
        for (int i = 0; i < 16; i++) {
            if (i < half) {
                float a = r[i], b = r[i + half];
                float sel = hi ? a : b;
                float got = __shfl_xor_sync(0xffffffffu, sel, m);
                r[i] = hi ? (b + got) : (a + got);
            }
        }
    }
    float s0 = (n - lane >= 0) ? (r[0] * 0.125f + pos_bias[lane * NH + h]) : NEG;

    // ---- sparse offsets (indices 32..43) ----
    float s1 = NEG;
#pragma unroll
    for (int oi = 32; oi < NOFF; oi++) {
        const int off = c_offs[oi];
        const int src = n - off;
        float sc = NEG;
        if (src >= 0) {
            const float2 k2 = *(const float2*)(qkv + (size_t)src * H3 + D + h * 64 + lane * 2);
            float p = q2.x * k2.x + q2.y * k2.y;
            p += __shfl_xor_sync(0xffffffffu, p, 16);
            p += __shfl_xor_sync(0xffffffffu, p, 8);
            p += __shfl_xor_sync(0xffffffffu, p, 4);
            p += __shfl_xor_sync(0xffffffffu, p, 2);
            p += __shfl_xor_sync(0xffffffffu, p, 1);
            sc = p * 0.125f + pos_bias[oi * NH + h];
        }
        if (lane == oi - 32) s1 = sc;
    }

    // ---- softmax ----
    float m = fmaxf(s0, s1);
    m = fmaxf(m, __shfl_xor_sync(0xffffffffu, m, 16));
    m = fmaxf(m, __shfl_xor_sync(0xffffffffu, m, 8));
    m = fmaxf(m, __shfl_xor_sync(0xffffffffu, m, 4));
    m = fmaxf(m, __shfl_xor_sync(0xffffffffu, m, 2));
    m = fmaxf(m, __shfl_xor_sync(0xffffffffu, m, 1));

    float e0 = (s0 > NEG) ? __expf(s0 - m) : 0.f;
    float e1 = (s1 > NEG) ? __expf(s1 - m) : 0.f;

    float sum = e0 + e1;
    sum += __shfl_xor_sync(0xffffffffu, sum, 16);
    sum += __shfl_xor_sync(0xffffffffu, sum, 8);
    sum += __shfl_xor_sync(0xffffffffu, sum, 4);
    sum += __shfl_xor_sync(0xffffffffu, sum, 2);
    sum += __shfl_xor_sync(0xffffffffu, sum, 1);
    const float inv = 1.f / sum;

    // ---- weighted V sum ----
    float acc0 = 0.f, acc1 = 0.f;
#pragma unroll
    for (int o = 0; o < NOFF; o++) {
        const int off = c_offs[o];
        const int src = n - off;
        if (src >= 0) {
            float ev = (o < 32) ? e0 : e1;
            float al = __shfl_sync(0xffffffffu, ev, o & 31);
            const float2 v2 = *(const float2*)(qkv + (size_t)src * H3 + 2 * D + h * 64 + lane * 2);
            acc0 = fmaf(al, v2.x, acc0);
            acc1 = fmaf(al, v2.y, acc1);
        }
    }
    acc0 *= inv;
    acc1 *= inv;

    const int oi = n * D + h * 64 + lane * 2;
    const float2 g2 = *(const float2*)(gate + oi);
    float v0 = acc0 * g2.x;
    float v1 = acc1 * g2.y;

    __nv_bfloat16 h0 = __float2bfloat16(v0);
    __nv_bfloat16 h1 = __float2bfloat16(v1);
    a2h[oi]     = h0;
    a2h[oi + 1] = h1;
    a2l[oi]     = __float2bfloat16(v0 - __bfloat162float(h0));
    a2l[oi + 1] = __float2bfloat16(v1 - __bfloat162float(h1));
}

// ---------------------------------------------------------------------------
// kernel_launch
// ---------------------------------------------------------------------------
extern "C" void kernel_launch(void* const* d_in, const int* in_sizes, int n_in,
                              void* d_out, int out_size)
{
    const float* x        = (const float*)d_in[0];
    const float* Wqkv     = (const float*)d_in[1];
    const float* bqkv     = (const float*)d_in[2];
    const float* Wout     = (const float*)d_in[3];
    const float* bout     = (const float*)d_in[4];
    const float* Wgate    = (const float*)d_in[5];
    const float* bgate    = (const float*)d_in[6];
    const float* pos_bias = (const float*)d_in[7];
    float* out = (float*)d_out;

    float *qkv, *gate;
    __nv_bfloat16 *xh, *xl, *wfh, *wfl, *woh, *wol, *a2h, *a2l;
    cudaGetSymbolAddress((void**)&qkv,  g_qkv);
    cudaGetSymbolAddress((void**)&gate, g_gate);
    cudaGetSymbolAddress((void**)&xh,  g_xh);  cudaGetSymbolAddress((void**)&xl,  g_xl);
    cudaGetSymbolAddress((void**)&wfh, g_wfh); cudaGetSymbolAddress((void**)&wfl, g_wfl);
    cudaGetSymbolAddress((void**)&woh, g_woh); cudaGetSymbolAddress((void**)&wol, g_wol);
    cudaGetSymbolAddress((void**)&a2h, g_a2h); cudaGetSymbolAddress((void**)&a2l, g_a2l);

    const int SMEM_GEMM = 128 + 2 * (2 * 64 * 128 + 2 * 128 * 128);  // 128 + 98304
    cudaFuncSetAttribute(hmma_gemm, cudaFuncAttributeMaxDynamicSharedMemorySize, SMEM_GEMM);

    // 1) all fp32 -> bf16 hi/lo splits
    split_all_kernel<<<(TOT4 + 255) / 256, 256>>>(
        (const float4*)x, (const float4*)Wqkv, (const float4*)Wgate, (const float4*)Wout,
        (uint2*)xh, (uint2*)xl, (uint2*)wfh, (uint2*)wfl, (uint2*)woh, (uint2*)wol);

    // 2) fused qkv+gate GEMM: [2048, 4096] = x @ [Wqkv; Wgate]^T   (1024 CTAs)
    hmma_gemm<<<dim3((H3 + D) / 128, TOK / 64), 256, SMEM_GEMM>>>(
        xh, xl, wfh, wfl, bqkv, bgate, qkv, gate, H3 + D, D, H3);

    // 3) attention + gate -> split a2
    attn_kernel<<<(TOK * NH) / 8, 256>>>(qkv, gate, pos_bias, a2h, a2l);

    // 4) out = a2 @ Wout^T + bout   (256 CTAs)
    hmma_gemm<<<dim3(D / 128, TOK / 64), 256, SMEM_GEMM>>>(
        a2h, a2l, woh, wol, bout, bout, out, nullptr, D, D, D);
}